// round 1
// baseline (speedup 1.0000x reference)
#include <cuda_runtime.h>
#include <math.h>

#define B_  2
#define S_  2048
#define D_  1024
#define H_  16
#define HD_ 64
#define M_  (B_*S_)          // 4096 rows in projection GEMMs
#define ALD 68               // smem leading dim (floats) for transposed tiles

// Scratch (allocation-free): Q/K/V in [b,h,s,hd], O in [b,s,d]
__device__ float g_Q[B_*H_*S_*HD_];
__device__ float g_K[B_*H_*S_*HD_];
__device__ float g_V[B_*H_*S_*HD_];
__device__ float g_O[B_*S_*D_];

// ---------------------------------------------------------------------------
// Tiled GEMM: Y[m,n] = sum_k X[m,k] * W[n,k]   (i.e. X @ W^T),  K = N = 1024
// outmode: 0/1/2 -> write g_Q/g_K/g_V in [b,h,s,hd] layout; 3 -> Yext row-major
// srcsel:  0 -> Xext, 1 -> g_O
// ---------------------------------------------------------------------------
__global__ __launch_bounds__(256) void gemm_kernel(
    const float* __restrict__ Xext, const float* __restrict__ W,
    float* __restrict__ Yext, int outmode, int srcsel)
{
    __shared__ __align__(16) float As[32][ALD];  // [k][m]
    __shared__ __align__(16) float Bs[32][ALD];  // [k][n]

    const float* X = srcsel ? g_O : Xext;
    int t  = threadIdx.x;
    int tx = t & 15, ty = t >> 4;
    int m0 = blockIdx.y << 6, n0 = blockIdx.x << 6;

    int lrow = t >> 3;          // 0..31
    int lc4  = (t & 7) << 2;    // 0..28

    float acc[4][4] = {};

    for (int k0 = 0; k0 < D_; k0 += 32) {
        #pragma unroll
        for (int rr = 0; rr < 64; rr += 32) {
            float4 a = *(const float4*)&X[(size_t)(m0 + lrow + rr) * D_ + k0 + lc4];
            float4 b = *(const float4*)&W[(size_t)(n0 + lrow + rr) * D_ + k0 + lc4];
            As[lc4+0][lrow+rr] = a.x; As[lc4+1][lrow+rr] = a.y;
            As[lc4+2][lrow+rr] = a.z; As[lc4+3][lrow+rr] = a.w;
            Bs[lc4+0][lrow+rr] = b.x; Bs[lc4+1][lrow+rr] = b.y;
            Bs[lc4+2][lrow+rr] = b.z; Bs[lc4+3][lrow+rr] = b.w;
        }
        __syncthreads();

        #pragma unroll
        for (int kk = 0; kk < 32; kk++) {
            float4 a4 = *(const float4*)&As[kk][ty << 2];
            float4 b4 = *(const float4*)&Bs[kk][tx << 2];
            float a[4] = {a4.x, a4.y, a4.z, a4.w};
            float b[4] = {b4.x, b4.y, b4.z, b4.w};
            #pragma unroll
            for (int i = 0; i < 4; i++)
                #pragma unroll
                for (int j = 0; j < 4; j++)
                    acc[i][j] = fmaf(a[i], b[j], acc[i][j]);
        }
        __syncthreads();
    }

    #pragma unroll
    for (int i = 0; i < 4; i++) {
        int m = m0 + (ty << 2) + i;
        #pragma unroll
        for (int j = 0; j < 4; j++) {
            int n = n0 + (tx << 2) + j;
            float v = acc[i][j];
            if (outmode == 3) {
                Yext[(size_t)m * D_ + n] = v;
            } else {
                int b = m >> 11, s = m & (S_ - 1);
                int h = n >> 6,  hd = n & 63;
                float* dst = (outmode == 0) ? g_Q : (outmode == 1 ? g_K : g_V);
                dst[(size_t)(((b << 4) | h) * S_ + s) * HD_ + hd] = v;
            }
        }
    }
}

// ---------------------------------------------------------------------------
// Flash-style attention. One CTA = 64 query rows of one (b,h).
// Faithful to reference: masked scores = -1e-9f (exact), applied after /8.
// ---------------------------------------------------------------------------
__global__ __launch_bounds__(256) void attn_kernel(const int* __restrict__ mask)
{
    extern __shared__ __align__(16) float sm[];
    float* QsT = sm;                 // [64 d][ALD m]
    float* KsT = sm + 64 * ALD;      // [64 d][ALD n]
    float* PsT = sm + 2 * 64 * ALD;  // [64 n][ALD m]
    float* Vs  = sm + 3 * 64 * ALD;  // [64 n][64 d]

    int t  = threadIdx.x;
    int r0 = (t >> 4) << 2;   // this thread's 4 rows (m)  = ty*4
    int c4 = (t & 15) << 2;   // this thread's 4 cols (n/d) = tx*4

    int bh = blockIdx.y;
    int b  = bh >> 4, h = bh & 15;
    int q0 = blockIdx.x << 6;

    const float* Qp = g_Q + ((size_t)bh * S_ + q0) * HD_;
    const float* Kp = g_K + (size_t)bh * S_ * HD_;
    const float* Vp = g_V + (size_t)bh * S_ * HD_;

    // Load Q tile, transposed to d-major
    {
        float4 v[4];
        #pragma unroll
        for (int i = 0; i < 4; i++)
            v[i] = *(const float4*)(Qp + (size_t)(r0 + i) * HD_ + c4);
        #pragma unroll
        for (int j = 0; j < 4; j++) {
            float4 w;
            w.x = ((const float*)&v[0])[j];
            w.y = ((const float*)&v[1])[j];
            w.z = ((const float*)&v[2])[j];
            w.w = ((const float*)&v[3])[j];
            *(float4*)&QsT[(c4 + j) * ALD + r0] = w;
        }
    }

    float m_i[4], l_i[4], acc[4][4];
    #pragma unroll
    for (int i = 0; i < 4; i++) {
        m_i[i] = -INFINITY; l_i[i] = 0.f;
        #pragma unroll
        for (int j = 0; j < 4; j++) acc[i][j] = 0.f;
    }

    for (int kv0 = 0; kv0 < S_; kv0 += 64) {
        // Load K (transposed) and V (natural)
        {
            float4 kv[4];
            #pragma unroll
            for (int i = 0; i < 4; i++) {
                kv[i] = *(const float4*)(Kp + (size_t)(kv0 + r0 + i) * HD_ + c4);
                float4 vv = *(const float4*)(Vp + (size_t)(kv0 + r0 + i) * HD_ + c4);
                *(float4*)&Vs[(r0 + i) * 64 + c4] = vv;
            }
            #pragma unroll
            for (int j = 0; j < 4; j++) {
                float4 w;
                w.x = ((const float*)&kv[0])[j];
                w.y = ((const float*)&kv[1])[j];
                w.z = ((const float*)&kv[2])[j];
                w.w = ((const float*)&kv[3])[j];
                *(float4*)&KsT[(c4 + j) * ALD + r0] = w;
            }
        }
        __syncthreads();

        // S = Q K^T
        float s[4][4] = {};
        #pragma unroll 8
        for (int d = 0; d < 64; d++) {
            float4 q4 = *(const float4*)&QsT[d * ALD + r0];
            float4 k4 = *(const float4*)&KsT[d * ALD + c4];
            float q[4] = {q4.x, q4.y, q4.z, q4.w};
            float k[4] = {k4.x, k4.y, k4.z, k4.w};
            #pragma unroll
            for (int i = 0; i < 4; i++)
                #pragma unroll
                for (int j = 0; j < 4; j++)
                    s[i][j] = fmaf(q[i], k[j], s[i][j]);
        }

        // scale, mask-fill (-1e-9 exact), online softmax update
        const int* mrow = mask + ((size_t)b * S_ + (q0 + r0)) * S_ + kv0 + c4;
        #pragma unroll
        for (int i = 0; i < 4; i++) {
            int4 mk = *(const int4*)(mrow + (size_t)i * S_);
            s[i][0] = (mk.x == 0) ? -1e-9f : s[i][0] * 0.125f;
            s[i][1] = (mk.y == 0) ? -1e-9f : s[i][1] * 0.125f;
            s[i][2] = (mk.z == 0) ? -1e-9f : s[i][2] * 0.125f;
            s[i][3] = (mk.w == 0) ? -1e-9f : s[i][3] * 0.125f;

            float tm = fmaxf(fmaxf(s[i][0], s[i][1]), fmaxf(s[i][2], s[i][3]));
            tm = fmaxf(tm, __shfl_xor_sync(0xffffffffu, tm, 8, 16));
            tm = fmaxf(tm, __shfl_xor_sync(0xffffffffu, tm, 4, 16));
            tm = fmaxf(tm, __shfl_xor_sync(0xffffffffu, tm, 2, 16));
            tm = fmaxf(tm, __shfl_xor_sync(0xffffffffu, tm, 1, 16));

            float mnew  = fmaxf(m_i[i], tm);
            float alpha = __expf(m_i[i] - mnew);
            m_i[i] = mnew;

            float rs = 0.f;
            #pragma unroll
            for (int j = 0; j < 4; j++) {
                float p = __expf(s[i][j] - mnew);
                s[i][j] = p;
                rs += p;
            }
            rs += __shfl_xor_sync(0xffffffffu, rs, 8, 16);
            rs += __shfl_xor_sync(0xffffffffu, rs, 4, 16);
            rs += __shfl_xor_sync(0xffffffffu, rs, 2, 16);
            rs += __shfl_xor_sync(0xffffffffu, rs, 1, 16);

            l_i[i] = l_i[i] * alpha + rs;
            #pragma unroll
            for (int j = 0; j < 4; j++) acc[i][j] *= alpha;
        }

        // Store P transposed (n-major)
        #pragma unroll
        for (int j = 0; j < 4; j++) {
            float4 w = make_float4(s[0][j], s[1][j], s[2][j], s[3][j]);
            *(float4*)&PsT[(c4 + j) * ALD + r0] = w;
        }
        __syncthreads();

        // O += P V
        #pragma unroll 8
        for (int n = 0; n < 64; n++) {
            float4 p4 = *(const float4*)&PsT[n * ALD + r0];
            float4 v4 = *(const float4*)&Vs[n * 64 + c4];
            float p[4] = {p4.x, p4.y, p4.z, p4.w};
            float v[4] = {v4.x, v4.y, v4.z, v4.w};
            #pragma unroll
            for (int i = 0; i < 4; i++)
                #pragma unroll
                for (int j = 0; j < 4; j++)
                    acc[i][j] = fmaf(p[i], v[j], acc[i][j]);
        }
        __syncthreads();
    }

    // epilogue: normalize, write O in [b,s,d_model]
    float* Op = g_O + ((size_t)b * S_ + q0) * D_ + h * HD_;
    #pragma unroll
    for (int i = 0; i < 4; i++) {
        float inv = 1.0f / l_i[i];
        float4 o = make_float4(acc[i][0] * inv, acc[i][1] * inv,
                               acc[i][2] * inv, acc[i][3] * inv);
        *(float4*)(Op + (size_t)(r0 + i) * D_ + c4) = o;
    }
}

// ---------------------------------------------------------------------------
extern "C" void kernel_launch(void* const* d_in, const int* in_sizes, int n_in,
                              void* d_out, int out_size)
{
    const float* X    = (const float*)d_in[0];
    const int*   mask = (const int*)d_in[1];
    const float* Wq   = (const float*)d_in[2];
    const float* Wk   = (const float*)d_in[3];
    const float* Wv   = (const float*)d_in[4];
    const float* Wo   = (const float*)d_in[5];
    float* out = (float*)d_out;

    size_t smem = (size_t)(3 * 64 * ALD + 64 * 64) * sizeof(float);  // 68608 B
    cudaFuncSetAttribute(attn_kernel,
                         cudaFuncAttributeMaxDynamicSharedMemorySize, (int)smem);

    dim3 gblk(256);
    dim3 ggrid(D_ / 64, M_ / 64);   // (16, 64)

    gemm_kernel<<<ggrid, gblk>>>(X, Wq, nullptr, 0, 0);
    gemm_kernel<<<ggrid, gblk>>>(X, Wk, nullptr, 1, 0);
    gemm_kernel<<<ggrid, gblk>>>(X, Wv, nullptr, 2, 0);

    attn_kernel<<<dim3(S_ / 64, B_ * H_), 256, smem>>>(mask);

    gemm_kernel<<<ggrid, gblk>>>(nullptr, Wo, out, 3, 1);
}

// round 2
// speedup vs baseline: 1.2116x; 1.2116x over previous
#include <cuda_runtime.h>
#include <math.h>
#include <stdint.h>

#define B_  2
#define S_  2048
#define D_  1024
#define H_  16
#define HD_ 64
#define M_  (B_*S_)          // 4096 rows in projection GEMMs
#define ALD 68               // smem leading dim (floats) for attn transposed tiles

// Scratch (allocation-free): Q/K/V in [b,h,s,hd], O in [b,s,d]
__device__ float g_Q[B_*H_*S_*HD_];
__device__ float g_K[B_*H_*S_*HD_];
__device__ float g_V[B_*H_*S_*HD_];
__device__ float g_O[B_*S_*D_];

// ---------------------------------------------------------------------------
// TF32 helpers (3xTF32 split precision: a = hi + lo, error ~2^-24)
// ---------------------------------------------------------------------------
__device__ __forceinline__ void split_tf32(float x, uint32_t& hi, uint32_t& lo) {
    uint32_t h;
    asm("cvt.rna.tf32.f32 %0, %1;" : "=r"(h) : "f"(x));
    float hf = __uint_as_float(h);
    asm("cvt.rna.tf32.f32 %0, %1;" : "=r"(lo) : "f"(x - hf));
    hi = h;
}

__device__ __forceinline__ void mma_tf32(float* d, const uint32_t* a, const uint32_t* b) {
    asm volatile(
        "mma.sync.aligned.m16n8k8.row.col.f32.tf32.tf32.f32 "
        "{%0,%1,%2,%3}, {%4,%5,%6,%7}, {%8,%9}, {%0,%1,%2,%3};"
        : "+f"(d[0]), "+f"(d[1]), "+f"(d[2]), "+f"(d[3])
        : "r"(a[0]), "r"(a[1]), "r"(a[2]), "r"(a[3]),
          "r"(b[0]), "r"(b[1]));
}

// ---------------------------------------------------------------------------
// Tensor-core GEMM: Y[m,n] = sum_k X[m,k] * W[n,k]  (X @ W^T), K = N = 1024
// BM=128, BN=128, BK=16, 256 threads = 8 warps (2x4), warp tile 64x32.
// 3xTF32 for fp32-grade accuracy.
// outmode: 0/1/2 -> write g_Q/g_K/g_V in [b,h,s,hd]; 3 -> Yext row-major
// srcsel:  0 -> Xext, 1 -> g_O
// ---------------------------------------------------------------------------
#define BK_ 16
#define LDA_ 20   // smem stride: (20*r + c) % 32 distinct over 8 rows x 4 cols

__global__ __launch_bounds__(256) void gemm_tc(
    const float* __restrict__ Xext, const float* __restrict__ W,
    float* __restrict__ Yext, int outmode, int srcsel)
{
    __shared__ __align__(16) float As[128][LDA_];
    __shared__ __align__(16) float Bs[128][LDA_];

    const float* X = srcsel ? g_O : Xext;
    int t    = threadIdx.x;
    int wid  = t >> 5, lane = t & 31;
    int wm   = wid >> 2, wn = wid & 3;          // warp grid 2x4
    int m0   = blockIdx.y << 7, n0 = blockIdx.x << 7;

    int lr = t >> 2;             // 0..63
    int lc = (t & 3) << 2;       // 0,4,8,12

    const float* Aptr = X + (size_t)(m0 + lr) * D_ + lc;
    const float* Bptr = W + (size_t)(n0 + lr) * D_ + lc;

    // register double-buffer prefetch
    float4 pa0 = *(const float4*)(Aptr);
    float4 pa1 = *(const float4*)(Aptr + (size_t)64 * D_);
    float4 pb0 = *(const float4*)(Bptr);
    float4 pb1 = *(const float4*)(Bptr + (size_t)64 * D_);

    float acc[4][4][4];          // [mtile][ntile][frag]
    #pragma unroll
    for (int i = 0; i < 4; i++)
        #pragma unroll
        for (int j = 0; j < 4; j++)
            #pragma unroll
            for (int q = 0; q < 4; q++) acc[i][j][q] = 0.f;

    int lq = lane >> 2;          // 0..7
    int lk = lane & 3;           // 0..3

    for (int k0 = 0; k0 < D_; k0 += BK_) {
        *(float4*)&As[lr     ][lc] = pa0;
        *(float4*)&As[lr + 64][lc] = pa1;
        *(float4*)&Bs[lr     ][lc] = pb0;
        *(float4*)&Bs[lr + 64][lc] = pb1;
        __syncthreads();

        if (k0 + BK_ < D_) {
            pa0 = *(const float4*)(Aptr + k0 + BK_);
            pa1 = *(const float4*)(Aptr + (size_t)64 * D_ + k0 + BK_);
            pb0 = *(const float4*)(Bptr + k0 + BK_);
            pb1 = *(const float4*)(Bptr + (size_t)64 * D_ + k0 + BK_);
        }

        #pragma unroll
        for (int ks = 0; ks < BK_; ks += 8) {
            uint32_t ah[4][4], al[4][4], bh[4][2], bl[4][2];

            #pragma unroll
            for (int mt = 0; mt < 4; mt++) {
                int row = (wm << 6) + (mt << 4) + lq;
                split_tf32(As[row    ][ks + lk    ], ah[mt][0], al[mt][0]);
                split_tf32(As[row + 8][ks + lk    ], ah[mt][1], al[mt][1]);
                split_tf32(As[row    ][ks + lk + 4], ah[mt][2], al[mt][2]);
                split_tf32(As[row + 8][ks + lk + 4], ah[mt][3], al[mt][3]);
            }
            #pragma unroll
            for (int nt = 0; nt < 4; nt++) {
                int col = (wn << 5) + (nt << 3) + lq;
                split_tf32(Bs[col][ks + lk    ], bh[nt][0], bl[nt][0]);
                split_tf32(Bs[col][ks + lk + 4], bh[nt][1], bl[nt][1]);
            }

            #pragma unroll
            for (int mt = 0; mt < 4; mt++)
                #pragma unroll
                for (int nt = 0; nt < 4; nt++) {
                    mma_tf32(acc[mt][nt], al[mt], bh[nt]);
                    mma_tf32(acc[mt][nt], ah[mt], bl[nt]);
                    mma_tf32(acc[mt][nt], ah[mt], bh[nt]);
                }
        }
        __syncthreads();
    }

    // epilogue: c0,c1 at (r, c),(r,c+1); c2,c3 at (r+8, c),(r+8,c+1)
    if (outmode == 3) {
        #pragma unroll
        for (int mt = 0; mt < 4; mt++) {
            int r = m0 + (wm << 6) + (mt << 4) + lq;
            #pragma unroll
            for (int nt = 0; nt < 4; nt++) {
                int c = n0 + (wn << 5) + (nt << 3) + (lk << 1);
                *(float2*)&Yext[(size_t)r * D_ + c] =
                    make_float2(acc[mt][nt][0], acc[mt][nt][1]);
                *(float2*)&Yext[(size_t)(r + 8) * D_ + c] =
                    make_float2(acc[mt][nt][2], acc[mt][nt][3]);
            }
        }
    } else {
        float* dst = (outmode == 0) ? g_Q : (outmode == 1 ? g_K : g_V);
        #pragma unroll
        for (int mt = 0; mt < 4; mt++) {
            int r = m0 + (wm << 6) + (mt << 4) + lq;
            #pragma unroll
            for (int nt = 0; nt < 4; nt++) {
                int c = n0 + (wn << 5) + (nt << 3) + (lk << 1);
                int h = c >> 6, hd = c & 63;
                {
                    int b = r >> 11, s = r & (S_ - 1);
                    *(float2*)&dst[(size_t)(((b << 4) | h) * S_ + s) * HD_ + hd] =
                        make_float2(acc[mt][nt][0], acc[mt][nt][1]);
                }
                {
                    int r2 = r + 8;
                    int b = r2 >> 11, s = r2 & (S_ - 1);
                    *(float2*)&dst[(size_t)(((b << 4) | h) * S_ + s) * HD_ + hd] =
                        make_float2(acc[mt][nt][2], acc[mt][nt][3]);
                }
            }
        }
    }
}

// ---------------------------------------------------------------------------
// Flash-style attention (unchanged this round). One CTA = 64 query rows of
// one (b,h). Faithful to reference: masked scores = -1e-9f exact, after /8.
// ---------------------------------------------------------------------------
__global__ __launch_bounds__(256) void attn_kernel(const int* __restrict__ mask)
{
    extern __shared__ __align__(16) float sm[];
    float* QsT = sm;                 // [64 d][ALD m]
    float* KsT = sm + 64 * ALD;      // [64 d][ALD n]
    float* PsT = sm + 2 * 64 * ALD;  // [64 n][ALD m]
    float* Vs  = sm + 3 * 64 * ALD;  // [64 n][64 d]

    int t  = threadIdx.x;
    int r0 = (t >> 4) << 2;
    int c4 = (t & 15) << 2;

    int bh = blockIdx.y;
    int b  = bh >> 4, h = bh & 15;
    int q0 = blockIdx.x << 6;

    const float* Qp = g_Q + ((size_t)bh * S_ + q0) * HD_;
    const float* Kp = g_K + (size_t)bh * S_ * HD_;
    const float* Vp = g_V + (size_t)bh * S_ * HD_;

    {
        float4 v[4];
        #pragma unroll
        for (int i = 0; i < 4; i++)
            v[i] = *(const float4*)(Qp + (size_t)(r0 + i) * HD_ + c4);
        #pragma unroll
        for (int j = 0; j < 4; j++) {
            float4 w;
            w.x = ((const float*)&v[0])[j];
            w.y = ((const float*)&v[1])[j];
            w.z = ((const float*)&v[2])[j];
            w.w = ((const float*)&v[3])[j];
            *(float4*)&QsT[(c4 + j) * ALD + r0] = w;
        }
    }

    float m_i[4], l_i[4], acc[4][4];
    #pragma unroll
    for (int i = 0; i < 4; i++) {
        m_i[i] = -INFINITY; l_i[i] = 0.f;
        #pragma unroll
        for (int j = 0; j < 4; j++) acc[i][j] = 0.f;
    }

    for (int kv0 = 0; kv0 < S_; kv0 += 64) {
        {
            float4 kv[4];
            #pragma unroll
            for (int i = 0; i < 4; i++) {
                kv[i] = *(const float4*)(Kp + (size_t)(kv0 + r0 + i) * HD_ + c4);
                float4 vv = *(const float4*)(Vp + (size_t)(kv0 + r0 + i) * HD_ + c4);
                *(float4*)&Vs[(r0 + i) * 64 + c4] = vv;
            }
            #pragma unroll
            for (int j = 0; j < 4; j++) {
                float4 w;
                w.x = ((const float*)&kv[0])[j];
                w.y = ((const float*)&kv[1])[j];
                w.z = ((const float*)&kv[2])[j];
                w.w = ((const float*)&kv[3])[j];
                *(float4*)&KsT[(c4 + j) * ALD + r0] = w;
            }
        }
        __syncthreads();

        float s[4][4] = {};
        #pragma unroll 8
        for (int d = 0; d < 64; d++) {
            float4 q4 = *(const float4*)&QsT[d * ALD + r0];
            float4 k4 = *(const float4*)&KsT[d * ALD + c4];
            float q[4] = {q4.x, q4.y, q4.z, q4.w};
            float k[4] = {k4.x, k4.y, k4.z, k4.w};
            #pragma unroll
            for (int i = 0; i < 4; i++)
                #pragma unroll
                for (int j = 0; j < 4; j++)
                    s[i][j] = fmaf(q[i], k[j], s[i][j]);
        }

        const int* mrow = mask + ((size_t)b * S_ + (q0 + r0)) * S_ + kv0 + c4;
        #pragma unroll
        for (int i = 0; i < 4; i++) {
            int4 mk = *(const int4*)(mrow + (size_t)i * S_);
            s[i][0] = (mk.x == 0) ? -1e-9f : s[i][0] * 0.125f;
            s[i][1] = (mk.y == 0) ? -1e-9f : s[i][1] * 0.125f;
            s[i][2] = (mk.z == 0) ? -1e-9f : s[i][2] * 0.125f;
            s[i][3] = (mk.w == 0) ? -1e-9f : s[i][3] * 0.125f;

            float tm = fmaxf(fmaxf(s[i][0], s[i][1]), fmaxf(s[i][2], s[i][3]));
            tm = fmaxf(tm, __shfl_xor_sync(0xffffffffu, tm, 8, 16));
            tm = fmaxf(tm, __shfl_xor_sync(0xffffffffu, tm, 4, 16));
            tm = fmaxf(tm, __shfl_xor_sync(0xffffffffu, tm, 2, 16));
            tm = fmaxf(tm, __shfl_xor_sync(0xffffffffu, tm, 1, 16));

            float mnew  = fmaxf(m_i[i], tm);
            float alpha = __expf(m_i[i] - mnew);
            m_i[i] = mnew;

            float rs = 0.f;
            #pragma unroll
            for (int j = 0; j < 4; j++) {
                float p = __expf(s[i][j] - mnew);
                s[i][j] = p;
                rs += p;
            }
            rs += __shfl_xor_sync(0xffffffffu, rs, 8, 16);
            rs += __shfl_xor_sync(0xffffffffu, rs, 4, 16);
            rs += __shfl_xor_sync(0xffffffffu, rs, 2, 16);
            rs += __shfl_xor_sync(0xffffffffu, rs, 1, 16);

            l_i[i] = l_i[i] * alpha + rs;
            #pragma unroll
            for (int j = 0; j < 4; j++) acc[i][j] *= alpha;
        }

        #pragma unroll
        for (int j = 0; j < 4; j++) {
            float4 w = make_float4(s[0][j], s[1][j], s[2][j], s[3][j]);
            *(float4*)&PsT[(c4 + j) * ALD + r0] = w;
        }
        __syncthreads();

        #pragma unroll 8
        for (int n = 0; n < 64; n++) {
            float4 p4 = *(const float4*)&PsT[n * ALD + r0];
            float4 v4 = *(const float4*)&Vs[n * 64 + c4];
            float p[4] = {p4.x, p4.y, p4.z, p4.w};
            float v[4] = {v4.x, v4.y, v4.z, v4.w};
            #pragma unroll
            for (int i = 0; i < 4; i++)
                #pragma unroll
                for (int j = 0; j < 4; j++)
                    acc[i][j] = fmaf(p[i], v[j], acc[i][j]);
        }
        __syncthreads();
    }

    float* Op = g_O + ((size_t)b * S_ + q0) * D_ + h * HD_;
    #pragma unroll
    for (int i = 0; i < 4; i++) {
        float inv = 1.0f / l_i[i];
        float4 o = make_float4(acc[i][0] * inv, acc[i][1] * inv,
                               acc[i][2] * inv, acc[i][3] * inv);
        *(float4*)(Op + (size_t)(r0 + i) * D_ + c4) = o;
    }
}

// ---------------------------------------------------------------------------
extern "C" void kernel_launch(void* const* d_in, const int* in_sizes, int n_in,
                              void* d_out, int out_size)
{
    const float* X    = (const float*)d_in[0];
    const int*   mask = (const int*)d_in[1];
    const float* Wq   = (const float*)d_in[2];
    const float* Wk   = (const float*)d_in[3];
    const float* Wv   = (const float*)d_in[4];
    const float* Wo   = (const float*)d_in[5];
    float* out = (float*)d_out;

    size_t smem = (size_t)(3 * 64 * ALD + 64 * 64) * sizeof(float);  // 68608 B
    cudaFuncSetAttribute(attn_kernel,
                         cudaFuncAttributeMaxDynamicSharedMemorySize, (int)smem);

    dim3 gblk(256);
    dim3 ggrid(D_ / 128, M_ / 128);   // (8, 32)

    gemm_tc<<<ggrid, gblk>>>(X, Wq, nullptr, 0, 0);
    gemm_tc<<<ggrid, gblk>>>(X, Wk, nullptr, 1, 0);
    gemm_tc<<<ggrid, gblk>>>(X, Wv, nullptr, 2, 0);

    attn_kernel<<<dim3(S_ / 64, B_ * H_), 256, smem>>>(mask);

    gemm_tc<<<ggrid, gblk>>>(nullptr, Wo, out, 3, 1);
}

// round 3
// speedup vs baseline: 1.8085x; 1.4926x over previous
#include <cuda_runtime.h>
#include <math.h>
#include <stdint.h>

#define B_  2
#define S_  2048
#define D_  1024
#define H_  16
#define HD_ 64
#define M_  (B_*S_)
#define WPR 64               // mask bit-words per query row (S/32)

// Scratch (allocation-free)
__device__ float    g_O[B_*S_*D_];
__device__ uint32_t g_Qh[B_*H_*S_*HD_/2], g_Ql[B_*H_*S_*HD_/2];
__device__ uint32_t g_Kh[B_*H_*S_*HD_/2], g_Kl[B_*H_*S_*HD_/2];
__device__ uint32_t g_Vh[B_*H_*S_*HD_/2], g_Vl[B_*H_*S_*HD_/2];
__device__ uint32_t g_mbits[B_*S_*WPR];

// ---------------------------------------------------------------------------
// helpers
// ---------------------------------------------------------------------------
__device__ __forceinline__ void split_tf32(float x, uint32_t& hi, uint32_t& lo) {
    uint32_t h;
    asm("cvt.rna.tf32.f32 %0, %1;" : "=r"(h) : "f"(x));
    float hf = __uint_as_float(h);
    asm("cvt.rna.tf32.f32 %0, %1;" : "=r"(lo) : "f"(x - hf));
    hi = h;
}

__device__ __forceinline__ void mma_tf32(float* d, const uint32_t* a, const uint32_t* b) {
    asm volatile(
        "mma.sync.aligned.m16n8k8.row.col.f32.tf32.tf32.f32 "
        "{%0,%1,%2,%3}, {%4,%5,%6,%7}, {%8,%9}, {%0,%1,%2,%3};"
        : "+f"(d[0]), "+f"(d[1]), "+f"(d[2]), "+f"(d[3])
        : "r"(a[0]), "r"(a[1]), "r"(a[2]), "r"(a[3]),
          "r"(b[0]), "r"(b[1]));
}

__device__ __forceinline__ void mma_bf16(float* d, const uint32_t* a,
                                         uint32_t b0, uint32_t b1) {
    asm volatile(
        "mma.sync.aligned.m16n8k16.row.col.f32.bf16.bf16.f32 "
        "{%0,%1,%2,%3}, {%4,%5,%6,%7}, {%8,%9}, {%0,%1,%2,%3};"
        : "+f"(d[0]), "+f"(d[1]), "+f"(d[2]), "+f"(d[3])
        : "r"(a[0]), "r"(a[1]), "r"(a[2]), "r"(a[3]),
          "r"(b0), "r"(b1));
}

// pack (v0 -> low half, v1 -> high half) as bf16x2, plus residual pack
__device__ __forceinline__ void pack_hl(float v0, float v1,
                                        uint32_t& hi, uint32_t& lo) {
    asm("cvt.rn.bf16x2.f32 %0, %1, %2;" : "=r"(hi) : "f"(v1), "f"(v0));
    float h0 = __uint_as_float(hi << 16);
    float h1 = __uint_as_float(hi & 0xffff0000u);
    asm("cvt.rn.bf16x2.f32 %0, %1, %2;" : "=r"(lo) : "f"(v1 - h1), "f"(v0 - h0));
}

__device__ __forceinline__ void ldm4(uint32_t& r0, uint32_t& r1, uint32_t& r2,
                                     uint32_t& r3, uint32_t addr) {
    asm volatile("ldmatrix.sync.aligned.m8n8.x4.shared.b16 {%0,%1,%2,%3}, [%4];"
                 : "=r"(r0), "=r"(r1), "=r"(r2), "=r"(r3) : "r"(addr));
}
__device__ __forceinline__ void ldm4t(uint32_t& r0, uint32_t& r1, uint32_t& r2,
                                      uint32_t& r3, uint32_t addr) {
    asm volatile("ldmatrix.sync.aligned.m8n8.x4.trans.shared.b16 {%0,%1,%2,%3}, [%4];"
                 : "=r"(r0), "=r"(r1), "=r"(r2), "=r"(r3) : "r"(addr));
}

// ---------------------------------------------------------------------------
// mask bit-packing: mask[b,1,q,kv] (int32) -> 1 bit per element
// ---------------------------------------------------------------------------
__global__ void pack_mask(const int* __restrict__ mask) {
    int warp  = (blockIdx.x * blockDim.x + threadIdx.x) >> 5;
    int lane  = threadIdx.x & 31;
    int nwarp = (gridDim.x * blockDim.x) >> 5;
    for (int w = warp; w < B_ * S_ * WPR; w += nwarp) {
        int v = mask[(size_t)w * 32 + lane];
        uint32_t bits = __ballot_sync(0xffffffffu, v != 0);
        if (lane == 0) g_mbits[w] = bits;
    }
}

// ---------------------------------------------------------------------------
// Tensor-core GEMM (3xTF32): Y[m,n] = sum_k X[m,k] * W[n,k]
// outmode 0/1/2 -> write bf16 hi/lo Q/K/V in [b,h,s,hd]; 3 -> Yext fp32
// ---------------------------------------------------------------------------
#define BK_  16
#define LDA_ 20

__global__ __launch_bounds__(256) void gemm_tc(
    const float* __restrict__ Xext, const float* __restrict__ W,
    float* __restrict__ Yext, int outmode, int srcsel)
{
    __shared__ __align__(16) float As[128][LDA_];
    __shared__ __align__(16) float Bs[128][LDA_];

    const float* X = srcsel ? g_O : Xext;
    int t    = threadIdx.x;
    int wid  = t >> 5, lane = t & 31;
    int wm   = wid >> 2, wn = wid & 3;
    int m0   = blockIdx.y << 7, n0 = blockIdx.x << 7;

    int lr = t >> 2;
    int lc = (t & 3) << 2;

    const float* Aptr = X + (size_t)(m0 + lr) * D_ + lc;
    const float* Bptr = W + (size_t)(n0 + lr) * D_ + lc;

    float4 pa0 = *(const float4*)(Aptr);
    float4 pa1 = *(const float4*)(Aptr + (size_t)64 * D_);
    float4 pb0 = *(const float4*)(Bptr);
    float4 pb1 = *(const float4*)(Bptr + (size_t)64 * D_);

    float acc[4][4][4];
    #pragma unroll
    for (int i = 0; i < 4; i++)
        #pragma unroll
        for (int j = 0; j < 4; j++)
            #pragma unroll
            for (int q = 0; q < 4; q++) acc[i][j][q] = 0.f;

    int lq = lane >> 2;
    int lk = lane & 3;

    for (int k0 = 0; k0 < D_; k0 += BK_) {
        *(float4*)&As[lr     ][lc] = pa0;
        *(float4*)&As[lr + 64][lc] = pa1;
        *(float4*)&Bs[lr     ][lc] = pb0;
        *(float4*)&Bs[lr + 64][lc] = pb1;
        __syncthreads();

        if (k0 + BK_ < D_) {
            pa0 = *(const float4*)(Aptr + k0 + BK_);
            pa1 = *(const float4*)(Aptr + (size_t)64 * D_ + k0 + BK_);
            pb0 = *(const float4*)(Bptr + k0 + BK_);
            pb1 = *(const float4*)(Bptr + (size_t)64 * D_ + k0 + BK_);
        }

        #pragma unroll
        for (int ks = 0; ks < BK_; ks += 8) {
            uint32_t ah[4][4], al[4][4], bh[4][2], bl[4][2];

            #pragma unroll
            for (int mt = 0; mt < 4; mt++) {
                int row = (wm << 6) + (mt << 4) + lq;
                split_tf32(As[row    ][ks + lk    ], ah[mt][0], al[mt][0]);
                split_tf32(As[row + 8][ks + lk    ], ah[mt][1], al[mt][1]);
                split_tf32(As[row    ][ks + lk + 4], ah[mt][2], al[mt][2]);
                split_tf32(As[row + 8][ks + lk + 4], ah[mt][3], al[mt][3]);
            }
            #pragma unroll
            for (int nt = 0; nt < 4; nt++) {
                int col = (wn << 5) + (nt << 3) + lq;
                split_tf32(Bs[col][ks + lk    ], bh[nt][0], bl[nt][0]);
                split_tf32(Bs[col][ks + lk + 4], bh[nt][1], bl[nt][1]);
            }

            #pragma unroll
            for (int mt = 0; mt < 4; mt++)
                #pragma unroll
                for (int nt = 0; nt < 4; nt++) {
                    mma_tf32(acc[mt][nt], al[mt], bh[nt]);
                    mma_tf32(acc[mt][nt], ah[mt], bl[nt]);
                    mma_tf32(acc[mt][nt], ah[mt], bh[nt]);
                }
        }
        __syncthreads();
    }

    if (outmode == 3) {
        #pragma unroll
        for (int mt = 0; mt < 4; mt++) {
            int r = m0 + (wm << 6) + (mt << 4) + lq;
            #pragma unroll
            for (int nt = 0; nt < 4; nt++) {
                int c = n0 + (wn << 5) + (nt << 3) + (lk << 1);
                *(float2*)&Yext[(size_t)r * D_ + c] =
                    make_float2(acc[mt][nt][0], acc[mt][nt][1]);
                *(float2*)&Yext[(size_t)(r + 8) * D_ + c] =
                    make_float2(acc[mt][nt][2], acc[mt][nt][3]);
            }
        }
    } else {
        uint32_t* dh = (outmode == 0) ? g_Qh : (outmode == 1 ? g_Kh : g_Vh);
        uint32_t* dl = (outmode == 0) ? g_Ql : (outmode == 1 ? g_Kl : g_Vl);
        #pragma unroll
        for (int mt = 0; mt < 4; mt++) {
            int r = m0 + (wm << 6) + (mt << 4) + lq;
            #pragma unroll
            for (int nt = 0; nt < 4; nt++) {
                int c  = n0 + (wn << 5) + (nt << 3) + (lk << 1);
                int h  = c >> 6, hd = c & 63;
                uint32_t hi, lo;
                {
                    int b = r >> 11, s = r & (S_ - 1);
                    size_t idx = ((size_t)(((b << 4) | h) * S_ + s) << 5) + (hd >> 1);
                    pack_hl(acc[mt][nt][0], acc[mt][nt][1], hi, lo);
                    dh[idx] = hi; dl[idx] = lo;
                }
                {
                    int r2 = r + 8;
                    int b = r2 >> 11, s = r2 & (S_ - 1);
                    size_t idx = ((size_t)(((b << 4) | h) * S_ + s) << 5) + (hd >> 1);
                    pack_hl(acc[mt][nt][2], acc[mt][nt][3], hi, lo);
                    dh[idx] = hi; dl[idx] = lo;
                }
            }
        }
    }
}

// ---------------------------------------------------------------------------
// Tensor-core flash attention (bf16 split). BQ=128 (8 warps x m16), BK=64.
// Masked scores = -1e-9f exact (after *0.125), matching reference.
// ---------------------------------------------------------------------------
#define VLDU 36   // smem row stride in uints (= 72 bf16 = 144B, conflict-free)

__global__ __launch_bounds__(256, 1) void attn_tc()
{
    __shared__ __align__(16) uint32_t sKh[64 * VLDU];
    __shared__ __align__(16) uint32_t sKl[64 * VLDU];
    __shared__ __align__(16) uint32_t sVh[64 * VLDU];
    __shared__ __align__(16) uint32_t sVl[64 * VLDU];

    int t = threadIdx.x, w = t >> 5, lane = t & 31;
    int r = lane >> 2, qt = lane & 3;
    int g8 = lane >> 3, l8 = lane & 7;

    int bh = blockIdx.y, b = bh >> 4, h = bh & 15;
    int q0 = blockIdx.x << 7;
    int qw = q0 + (w << 4);

    // ---- load Q A-fragments once (hi/lo), kept in registers ----
    uint32_t qah[4][4], qal[4][4];
    {
        const uint32_t* Qh = g_Qh + ((size_t)bh * S_ + qw) * 32;
        const uint32_t* Ql = g_Ql + ((size_t)bh * S_ + qw) * 32;
        #pragma unroll
        for (int ks = 0; ks < 4; ks++) {
            int i0 = r * 32 + ks * 8 + qt;
            qah[ks][0] = Qh[i0];           qah[ks][1] = Qh[i0 + 256];
            qah[ks][2] = Qh[i0 + 4];       qah[ks][3] = Qh[i0 + 260];
            qal[ks][0] = Ql[i0];           qal[ks][1] = Ql[i0 + 256];
            qal[ks][2] = Ql[i0 + 4];       qal[ks][3] = Ql[i0 + 260];
        }
    }

    float oacc[8][4];
    #pragma unroll
    for (int i = 0; i < 8; i++)
        #pragma unroll
        for (int j = 0; j < 4; j++) oacc[i][j] = 0.f;
    float mi0 = -INFINITY, mi1 = -INFINITY, li0 = 0.f, li1 = 0.f;

    const uint32_t* Kh = g_Kh + (size_t)bh * S_ * 32;
    const uint32_t* Kl = g_Kl + (size_t)bh * S_ * 32;
    const uint32_t* Vh = g_Vh + (size_t)bh * S_ * 32;
    const uint32_t* Vl = g_Vl + (size_t)bh * S_ * 32;
    const uint32_t* mbase = g_mbits + ((size_t)b * S_ + qw) * WPR;

    int lrow = t >> 2;           // 0..63
    int lcol = (t & 3) << 3;     // 0,8,16,24 uints

    for (int kv0 = 0; kv0 < S_; kv0 += 64) {
        // ---- cooperative smem fill (hi/lo K and V) ----
        {
            size_t s0 = (size_t)(kv0 + lrow) * 32 + lcol;
            int d0 = lrow * VLDU + lcol;
            uint4 a, c;
            a = *(const uint4*)(Kh + s0); c = *(const uint4*)(Kh + s0 + 4);
            *(uint4*)&sKh[d0] = a; *(uint4*)&sKh[d0 + 4] = c;
            a = *(const uint4*)(Kl + s0); c = *(const uint4*)(Kl + s0 + 4);
            *(uint4*)&sKl[d0] = a; *(uint4*)&sKl[d0 + 4] = c;
            a = *(const uint4*)(Vh + s0); c = *(const uint4*)(Vh + s0 + 4);
            *(uint4*)&sVh[d0] = a; *(uint4*)&sVh[d0 + 4] = c;
            a = *(const uint4*)(Vl + s0); c = *(const uint4*)(Vl + s0 + 4);
            *(uint4*)&sVl[d0] = a; *(uint4*)&sVl[d0 + 4] = c;
        }
        __syncthreads();

        // ---- S = Q K^T (bf16x3) ----
        float sacc[8][4];
        #pragma unroll
        for (int i = 0; i < 8; i++)
            #pragma unroll
            for (int j = 0; j < 4; j++) sacc[i][j] = 0.f;

        #pragma unroll
        for (int ks = 0; ks < 4; ks++) {
            #pragma unroll
            for (int ntp = 0; ntp < 4; ntp++) {
                int row = (ntp << 4) + ((g8 & 2) ? 8 : 0) + l8;
                int col = (ks << 3) + ((g8 & 1) ? 4 : 0);
                uint32_t ah = (uint32_t)__cvta_generic_to_shared(&sKh[row * VLDU + col]);
                uint32_t al = (uint32_t)__cvta_generic_to_shared(&sKl[row * VLDU + col]);
                uint32_t h0, h1, h2, h3, l0, l1, l2, l3;
                ldm4(h0, h1, h2, h3, ah);
                ldm4(l0, l1, l2, l3, al);
                mma_bf16(sacc[2*ntp],   qal[ks], h0, h1);
                mma_bf16(sacc[2*ntp],   qah[ks], l0, l1);
                mma_bf16(sacc[2*ntp],   qah[ks], h0, h1);
                mma_bf16(sacc[2*ntp+1], qal[ks], h2, h3);
                mma_bf16(sacc[2*ntp+1], qah[ks], l2, l3);
                mma_bf16(sacc[2*ntp+1], qah[ks], h2, h3);
            }
        }

        // ---- mask + scale (exact reference semantics) ----
        {
            const uint32_t* mb = mbase + (kv0 >> 5);
            uint32_t w0a = mb[(size_t)r * WPR];
            uint32_t w0b = mb[(size_t)r * WPR + 1];
            uint32_t w1a = mb[(size_t)(r + 8) * WPR];
            uint32_t w1b = mb[(size_t)(r + 8) * WPR + 1];
            #pragma unroll
            for (int nt = 0; nt < 8; nt++) {
                uint32_t wlo = (nt < 4) ? w0a : w0b;
                uint32_t whi = (nt < 4) ? w1a : w1b;
                int base = ((nt & 3) << 3) + (qt << 1);
                sacc[nt][0] = ((wlo >> base)       & 1) ? sacc[nt][0] * 0.125f : -1e-9f;
                sacc[nt][1] = ((wlo >> (base + 1)) & 1) ? sacc[nt][1] * 0.125f : -1e-9f;
                sacc[nt][2] = ((whi >> base)       & 1) ? sacc[nt][2] * 0.125f : -1e-9f;
                sacc[nt][3] = ((whi >> (base + 1)) & 1) ? sacc[nt][3] * 0.125f : -1e-9f;
            }
        }

        // ---- online softmax (rows r and r+8) ----
        float mx0 = -INFINITY, mx1 = -INFINITY;
        #pragma unroll
        for (int nt = 0; nt < 8; nt++) {
            mx0 = fmaxf(mx0, fmaxf(sacc[nt][0], sacc[nt][1]));
            mx1 = fmaxf(mx1, fmaxf(sacc[nt][2], sacc[nt][3]));
        }
        mx0 = fmaxf(mx0, __shfl_xor_sync(0xffffffffu, mx0, 1));
        mx0 = fmaxf(mx0, __shfl_xor_sync(0xffffffffu, mx0, 2));
        mx1 = fmaxf(mx1, __shfl_xor_sync(0xffffffffu, mx1, 1));
        mx1 = fmaxf(mx1, __shfl_xor_sync(0xffffffffu, mx1, 2));

        float mn0 = fmaxf(mi0, mx0), mn1 = fmaxf(mi1, mx1);
        float al0 = __expf(mi0 - mn0), al1 = __expf(mi1 - mn1);
        mi0 = mn0; mi1 = mn1;

        float rs0 = 0.f, rs1 = 0.f;
        #pragma unroll
        for (int nt = 0; nt < 8; nt++) {
            sacc[nt][0] = __expf(sacc[nt][0] - mn0);
            sacc[nt][1] = __expf(sacc[nt][1] - mn0);
            sacc[nt][2] = __expf(sacc[nt][2] - mn1);
            sacc[nt][3] = __expf(sacc[nt][3] - mn1);
            rs0 += sacc[nt][0] + sacc[nt][1];
            rs1 += sacc[nt][2] + sacc[nt][3];
        }
        rs0 += __shfl_xor_sync(0xffffffffu, rs0, 1);
        rs0 += __shfl_xor_sync(0xffffffffu, rs0, 2);
        rs1 += __shfl_xor_sync(0xffffffffu, rs1, 1);
        rs1 += __shfl_xor_sync(0xffffffffu, rs1, 2);

        li0 = li0 * al0 + rs0;
        li1 = li1 * al1 + rs1;
        #pragma unroll
        for (int nt = 0; nt < 8; nt++) {
            oacc[nt][0] *= al0; oacc[nt][1] *= al0;
            oacc[nt][2] *= al1; oacc[nt][3] *= al1;
        }

        // ---- pack P into A-fragments (hi/lo) ----
        uint32_t pah[4][4], pal[4][4];
        #pragma unroll
        for (int ks = 0; ks < 4; ks++) {
            pack_hl(sacc[2*ks][0],   sacc[2*ks][1],   pah[ks][0], pal[ks][0]);
            pack_hl(sacc[2*ks][2],   sacc[2*ks][3],   pah[ks][1], pal[ks][1]);
            pack_hl(sacc[2*ks+1][0], sacc[2*ks+1][1], pah[ks][2], pal[ks][2]);
            pack_hl(sacc[2*ks+1][2], sacc[2*ks+1][3], pah[ks][3], pal[ks][3]);
        }

        // ---- O += P V (bf16x3) ----
        #pragma unroll
        for (int ks = 0; ks < 4; ks++) {
            #pragma unroll
            for (int ntp = 0; ntp < 4; ntp++) {
                int row = (ks << 4) + ((g8 & 1) ? 8 : 0) + l8;
                int col = (ntp << 3) + ((g8 & 2) ? 4 : 0);
                uint32_t ah = (uint32_t)__cvta_generic_to_shared(&sVh[row * VLDU + col]);
                uint32_t al = (uint32_t)__cvta_generic_to_shared(&sVl[row * VLDU + col]);
                uint32_t h0, h1, h2, h3, l0, l1, l2, l3;
                ldm4t(h0, h1, h2, h3, ah);
                ldm4t(l0, l1, l2, l3, al);
                mma_bf16(oacc[2*ntp],   pal[ks], h0, h1);
                mma_bf16(oacc[2*ntp],   pah[ks], l0, l1);
                mma_bf16(oacc[2*ntp],   pah[ks], h0, h1);
                mma_bf16(oacc[2*ntp+1], pal[ks], h2, h3);
                mma_bf16(oacc[2*ntp+1], pah[ks], l2, l3);
                mma_bf16(oacc[2*ntp+1], pah[ks], h2, h3);
            }
        }
        __syncthreads();
    }

    // ---- epilogue: normalize, write O [b,s,d] fp32 ----
    float inv0 = 1.0f / li0, inv1 = 1.0f / li1;
    float* Op = g_O + ((size_t)b * S_ + qw) * D_ + h * 64;
    #pragma unroll
    for (int nt = 0; nt < 8; nt++) {
        int c = (nt << 3) + (qt << 1);
        *(float2*)&Op[(size_t)r * D_ + c] =
            make_float2(oacc[nt][0] * inv0, oacc[nt][1] * inv0);
        *(float2*)&Op[(size_t)(r + 8) * D_ + c] =
            make_float2(oacc[nt][2] * inv1, oacc[nt][3] * inv1);
    }
}

// ---------------------------------------------------------------------------
extern "C" void kernel_launch(void* const* d_in, const int* in_sizes, int n_in,
                              void* d_out, int out_size)
{
    const float* X    = (const float*)d_in[0];
    const int*   mask = (const int*)d_in[1];
    const float* Wq   = (const float*)d_in[2];
    const float* Wk   = (const float*)d_in[3];
    const float* Wv   = (const float*)d_in[4];
    const float* Wo   = (const float*)d_in[5];
    float* out = (float*)d_out;

    dim3 gblk(256);
    dim3 ggrid(D_ / 128, M_ / 128);

    pack_mask<<<2048, 256>>>(mask);
    gemm_tc<<<ggrid, gblk>>>(X, Wq, nullptr, 0, 0);
    gemm_tc<<<ggrid, gblk>>>(X, Wk, nullptr, 1, 0);
    gemm_tc<<<ggrid, gblk>>>(X, Wv, nullptr, 2, 0);

    attn_tc<<<dim3(S_ / 128, B_ * H_), 256>>>();

    gemm_tc<<<ggrid, gblk>>>(nullptr, Wo, out, 3, 1);
}

// round 5
// speedup vs baseline: 2.5153x; 1.3908x over previous
#include <cuda_runtime.h>
#include <math.h>
#include <stdint.h>

#define B_  2
#define S_  2048
#define D_  1024
#define H_  16
#define HD_ 64
#define M_  (B_*S_)
#define WPR 64               // mask bit-words per query row (S/32)
#define KU_ (D_/2)           // row stride in uint32 (bf16x2) = 512
#define WSZ (D_*D_/2)        // one weight matrix in uint32 = 524288

// Scratch (allocation-free), all bf16x2-packed hi/lo pairs
__device__ uint32_t g_Xh[M_*KU_],  g_Xl[M_*KU_];
__device__ uint32_t g_Wh[4*WSZ],   g_Wl[4*WSZ];       // Wq,Wk,Wv,Wo
__device__ uint32_t g_Oh[M_*KU_],  g_Ol[M_*KU_];
__device__ uint32_t g_Qh[B_*H_*S_*HD_/2], g_Ql[B_*H_*S_*HD_/2];
__device__ uint32_t g_Kh[B_*H_*S_*HD_/2], g_Kl[B_*H_*S_*HD_/2];
__device__ uint32_t g_Vh[B_*H_*S_*HD_/2], g_Vl[B_*H_*S_*HD_/2];
__device__ uint32_t g_mbits[B_*S_*WPR];

// ---------------------------------------------------------------------------
// helpers
// ---------------------------------------------------------------------------
__device__ __forceinline__ void mma_bf16(float* d, const uint32_t* a,
                                         uint32_t b0, uint32_t b1) {
    asm volatile(
        "mma.sync.aligned.m16n8k16.row.col.f32.bf16.bf16.f32 "
        "{%0,%1,%2,%3}, {%4,%5,%6,%7}, {%8,%9}, {%0,%1,%2,%3};"
        : "+f"(d[0]), "+f"(d[1]), "+f"(d[2]), "+f"(d[3])
        : "r"(a[0]), "r"(a[1]), "r"(a[2]), "r"(a[3]),
          "r"(b0), "r"(b1));
}

// pack (v0 -> low half, v1 -> high half) as bf16x2, plus residual pack
__device__ __forceinline__ void pack_hl(float v0, float v1,
                                        uint32_t& hi, uint32_t& lo) {
    asm("cvt.rn.bf16x2.f32 %0, %1, %2;" : "=r"(hi) : "f"(v1), "f"(v0));
    float h0 = __uint_as_float(hi << 16);
    float h1 = __uint_as_float(hi & 0xffff0000u);
    asm("cvt.rn.bf16x2.f32 %0, %1, %2;" : "=r"(lo) : "f"(v1 - h1), "f"(v0 - h0));
}

__device__ __forceinline__ void ldm4(uint32_t& r0, uint32_t& r1, uint32_t& r2,
                                     uint32_t& r3, uint32_t addr) {
    asm volatile("ldmatrix.sync.aligned.m8n8.x4.shared.b16 {%0,%1,%2,%3}, [%4];"
                 : "=r"(r0), "=r"(r1), "=r"(r2), "=r"(r3) : "r"(addr));
}
__device__ __forceinline__ void ldm4t(uint32_t& r0, uint32_t& r1, uint32_t& r2,
                                      uint32_t& r3, uint32_t addr) {
    asm volatile("ldmatrix.sync.aligned.m8n8.x4.trans.shared.b16 {%0,%1,%2,%3}, [%4];"
                 : "=r"(r0), "=r"(r1), "=r"(r2), "=r"(r3) : "r"(addr));
}

// ---------------------------------------------------------------------------
// fp32 -> bf16 hi/lo split. Destination selected IN DEVICE CODE (dsel):
// 0 -> g_Xh/g_Xl ; 1..4 -> g_Wh/g_Wl slot (Wq,Wk,Wv,Wo).
// (Device-global symbols must never be passed as host-side kernel args.)
// ---------------------------------------------------------------------------
__global__ void prep_split(const float* __restrict__ src, int dsel, int npairs) {
    uint32_t* dh;
    uint32_t* dl;
    if (dsel == 0) { dh = g_Xh; dl = g_Xl; }
    else {
        dh = g_Wh + (size_t)(dsel - 1) * WSZ;
        dl = g_Wl + (size_t)(dsel - 1) * WSZ;
    }
    int i0 = blockIdx.x * blockDim.x + threadIdx.x;
    int stride = gridDim.x * blockDim.x;
    for (int i = i0; i < npairs; i += stride) {
        float2 v = ((const float2*)src)[i];
        uint32_t hi, lo;
        pack_hl(v.x, v.y, hi, lo);
        dh[i] = hi; dl[i] = lo;
    }
}

// ---------------------------------------------------------------------------
// mask bit-packing
// ---------------------------------------------------------------------------
__global__ void pack_mask(const int* __restrict__ mask) {
    int warp  = (blockIdx.x * blockDim.x + threadIdx.x) >> 5;
    int lane  = threadIdx.x & 31;
    int nwarp = (gridDim.x * blockDim.x) >> 5;
    for (int w = warp; w < B_ * S_ * WPR; w += nwarp) {
        int v = mask[(size_t)w * 32 + lane];
        uint32_t bits = __ballot_sync(0xffffffffu, v != 0);
        if (lane == 0) g_mbits[w] = bits;
    }
}

// ---------------------------------------------------------------------------
// bf16x3 tensor-core GEMM: Y[m,n] = sum_k A[m,k]*B[n,k], pre-split operands.
// BM=BN=128, BK=32, 256 thr = 8 warps (2x4), warp tile 64x32.
// modep==0: A=g_X, B=W[blockIdx.z], epilogue -> Q/K/V bf16 hi/lo.
// modep==3: A=g_O, B=Wo, epilogue -> fp32 Yext.
// Operand pointers resolved in device code.
// ---------------------------------------------------------------------------
#define LDU 20   // smem row stride in uint32 (=40 bf16), conflict-free ldmatrix

__global__ __launch_bounds__(256) void gemm_bf16(float* __restrict__ Yext,
                                                 int modep)
{
    __shared__ __align__(16) uint32_t sAh[128*LDU], sAl[128*LDU];
    __shared__ __align__(16) uint32_t sBh[128*LDU], sBl[128*LDU];

    int z = blockIdx.z;
    int outmode = (modep == 3) ? 3 : z;

    const uint32_t *Ah, *Al, *Bh, *Bl;
    if (modep == 3) {
        Ah = g_Oh; Al = g_Ol;
        Bh = g_Wh + (size_t)3 * WSZ; Bl = g_Wl + (size_t)3 * WSZ;
    } else {
        Ah = g_Xh; Al = g_Xl;
        Bh = g_Wh + (size_t)z * WSZ; Bl = g_Wl + (size_t)z * WSZ;
    }

    int t = threadIdx.x, wid = t >> 5, lane = t & 31;
    int wm = wid >> 2, wn = wid & 3;
    int m0 = blockIdx.y << 7, n0 = blockIdx.x << 7;

    int lr  = t >> 1;            // 0..127
    int lcu = (t & 1) << 3;      // 0 or 8

    const uint32_t* pAh = Ah + (size_t)(m0 + lr) * KU_ + lcu;
    const uint32_t* pAl = Al + (size_t)(m0 + lr) * KU_ + lcu;
    const uint32_t* pBh = Bh + (size_t)(n0 + lr) * KU_ + lcu;
    const uint32_t* pBl = Bl + (size_t)(n0 + lr) * KU_ + lcu;

    uint4 rah0 = *(const uint4*)(pAh), rah1 = *(const uint4*)(pAh + 4);
    uint4 ral0 = *(const uint4*)(pAl), ral1 = *(const uint4*)(pAl + 4);
    uint4 rbh0 = *(const uint4*)(pBh), rbh1 = *(const uint4*)(pBh + 4);
    uint4 rbl0 = *(const uint4*)(pBl), rbl1 = *(const uint4*)(pBl + 4);

    float acc[4][4][4];
    #pragma unroll
    for (int i = 0; i < 4; i++)
        #pragma unroll
        for (int j = 0; j < 4; j++)
            #pragma unroll
            for (int q = 0; q < 4; q++) acc[i][j][q] = 0.f;

    // ldmatrix lane addressing (in uint32 units)
    int a_row = (lane & 15);
    int a_col = (lane >> 4) << 2;                       // 0 or 4
    int b_row = ((lane >> 4) << 3) + (lane & 7);        // 0..15
    int b_col = ((lane >> 3) & 1) << 2;                 // 0 or 4

    int sd = lr * LDU + lcu;

    for (int ku = 0; ku < KU_; ku += 16) {
        *(uint4*)&sAh[sd] = rah0; *(uint4*)&sAh[sd + 4] = rah1;
        *(uint4*)&sAl[sd] = ral0; *(uint4*)&sAl[sd + 4] = ral1;
        *(uint4*)&sBh[sd] = rbh0; *(uint4*)&sBh[sd + 4] = rbh1;
        *(uint4*)&sBl[sd] = rbl0; *(uint4*)&sBl[sd + 4] = rbl1;
        __syncthreads();

        if (ku + 16 < KU_) {
            rah0 = *(const uint4*)(pAh + ku + 16); rah1 = *(const uint4*)(pAh + ku + 20);
            ral0 = *(const uint4*)(pAl + ku + 16); ral1 = *(const uint4*)(pAl + ku + 20);
            rbh0 = *(const uint4*)(pBh + ku + 16); rbh1 = *(const uint4*)(pBh + ku + 20);
            rbl0 = *(const uint4*)(pBl + ku + 16); rbl1 = *(const uint4*)(pBl + ku + 20);
        }

        #pragma unroll
        for (int ch = 0; ch < 2; ch++) {
            int kc = ch << 3;       // chunk base in uints
            uint32_t ah[4][4], al[4][4], bh[4][2], bl[4][2];

            #pragma unroll
            for (int mt = 0; mt < 4; mt++) {
                int off = ((wm << 6) + (mt << 4) + a_row) * LDU + kc + a_col;
                uint32_t addr_h = (uint32_t)__cvta_generic_to_shared(&sAh[off]);
                uint32_t addr_l = (uint32_t)__cvta_generic_to_shared(&sAl[off]);
                ldm4(ah[mt][0], ah[mt][1], ah[mt][2], ah[mt][3], addr_h);
                ldm4(al[mt][0], al[mt][1], al[mt][2], al[mt][3], addr_l);
            }
            #pragma unroll
            for (int np = 0; np < 2; np++) {
                int off = ((wn << 5) + (np << 4) + b_row) * LDU + kc + b_col;
                uint32_t addr_h = (uint32_t)__cvta_generic_to_shared(&sBh[off]);
                uint32_t addr_l = (uint32_t)__cvta_generic_to_shared(&sBl[off]);
                ldm4(bh[2*np][0], bh[2*np][1], bh[2*np+1][0], bh[2*np+1][1], addr_h);
                ldm4(bl[2*np][0], bl[2*np][1], bl[2*np+1][0], bl[2*np+1][1], addr_l);
            }

            #pragma unroll
            for (int mt = 0; mt < 4; mt++)
                #pragma unroll
                for (int nt = 0; nt < 4; nt++) {
                    mma_bf16(acc[mt][nt], al[mt], bh[nt][0], bh[nt][1]);
                    mma_bf16(acc[mt][nt], ah[mt], bl[nt][0], bl[nt][1]);
                    mma_bf16(acc[mt][nt], ah[mt], bh[nt][0], bh[nt][1]);
                }
        }
        __syncthreads();
    }

    int lq = lane >> 2, lk = lane & 3;

    if (outmode == 3) {
        #pragma unroll
        for (int mt = 0; mt < 4; mt++) {
            int r = m0 + (wm << 6) + (mt << 4) + lq;
            #pragma unroll
            for (int nt = 0; nt < 4; nt++) {
                int c = n0 + (wn << 5) + (nt << 3) + (lk << 1);
                *(float2*)&Yext[(size_t)r * D_ + c] =
                    make_float2(acc[mt][nt][0], acc[mt][nt][1]);
                *(float2*)&Yext[(size_t)(r + 8) * D_ + c] =
                    make_float2(acc[mt][nt][2], acc[mt][nt][3]);
            }
        }
    } else {
        uint32_t* dh = (outmode == 0) ? g_Qh : (outmode == 1 ? g_Kh : g_Vh);
        uint32_t* dl = (outmode == 0) ? g_Ql : (outmode == 1 ? g_Kl : g_Vl);
        #pragma unroll
        for (int mt = 0; mt < 4; mt++) {
            int r = m0 + (wm << 6) + (mt << 4) + lq;
            #pragma unroll
            for (int nt = 0; nt < 4; nt++) {
                int c  = n0 + (wn << 5) + (nt << 3) + (lk << 1);
                int h  = c >> 6, hd = c & 63;
                uint32_t hi, lo;
                {
                    int b = r >> 11, s = r & (S_ - 1);
                    size_t idx = ((size_t)(((b << 4) | h) * S_ + s) << 5) + (hd >> 1);
                    pack_hl(acc[mt][nt][0], acc[mt][nt][1], hi, lo);
                    dh[idx] = hi; dl[idx] = lo;
                }
                {
                    int r2 = r + 8;
                    int b = r2 >> 11, s = r2 & (S_ - 1);
                    size_t idx = ((size_t)(((b << 4) | h) * S_ + s) << 5) + (hd >> 1);
                    pack_hl(acc[mt][nt][2], acc[mt][nt][3], hi, lo);
                    dh[idx] = hi; dl[idx] = lo;
                }
            }
        }
    }
}

// ---------------------------------------------------------------------------
// Tensor-core flash attention (bf16x3). BQ=128 (8 warps x m16), BK=64.
// Masked scores = -1e-9f exact (after *0.125), matching reference.
// Epilogue writes O as bf16 hi/lo for the O-projection GEMM.
// ---------------------------------------------------------------------------
#define VLDU 36

__global__ __launch_bounds__(256, 1) void attn_tc()
{
    __shared__ __align__(16) uint32_t sKh[64 * VLDU];
    __shared__ __align__(16) uint32_t sKl[64 * VLDU];
    __shared__ __align__(16) uint32_t sVh[64 * VLDU];
    __shared__ __align__(16) uint32_t sVl[64 * VLDU];

    int t = threadIdx.x, w = t >> 5, lane = t & 31;
    int r = lane >> 2, qt = lane & 3;
    int g8 = lane >> 3, l8 = lane & 7;

    int bh = blockIdx.y, b = bh >> 4, h = bh & 15;
    int q0 = blockIdx.x << 7;
    int qw = q0 + (w << 4);

    uint32_t qah[4][4], qal[4][4];
    {
        const uint32_t* Qh = g_Qh + ((size_t)bh * S_ + qw) * 32;
        const uint32_t* Ql = g_Ql + ((size_t)bh * S_ + qw) * 32;
        #pragma unroll
        for (int ks = 0; ks < 4; ks++) {
            int i0 = r * 32 + ks * 8 + qt;
            qah[ks][0] = Qh[i0];           qah[ks][1] = Qh[i0 + 256];
            qah[ks][2] = Qh[i0 + 4];       qah[ks][3] = Qh[i0 + 260];
            qal[ks][0] = Ql[i0];           qal[ks][1] = Ql[i0 + 256];
            qal[ks][2] = Ql[i0 + 4];       qal[ks][3] = Ql[i0 + 260];
        }
    }

    float oacc[8][4];
    #pragma unroll
    for (int i = 0; i < 8; i++)
        #pragma unroll
        for (int j = 0; j < 4; j++) oacc[i][j] = 0.f;
    float mi0 = -INFINITY, mi1 = -INFINITY, li0 = 0.f, li1 = 0.f;

    const uint32_t* Kh = g_Kh + (size_t)bh * S_ * 32;
    const uint32_t* Kl = g_Kl + (size_t)bh * S_ * 32;
    const uint32_t* Vh = g_Vh + (size_t)bh * S_ * 32;
    const uint32_t* Vl = g_Vl + (size_t)bh * S_ * 32;
    const uint32_t* mbase = g_mbits + ((size_t)b * S_ + qw) * WPR;

    int lrow = t >> 2;
    int lcol = (t & 3) << 3;

    for (int kv0 = 0; kv0 < S_; kv0 += 64) {
        {
            size_t s0 = (size_t)(kv0 + lrow) * 32 + lcol;
            int d0 = lrow * VLDU + lcol;
            uint4 a, c;
            a = *(const uint4*)(Kh + s0); c = *(const uint4*)(Kh + s0 + 4);
            *(uint4*)&sKh[d0] = a; *(uint4*)&sKh[d0 + 4] = c;
            a = *(const uint4*)(Kl + s0); c = *(const uint4*)(Kl + s0 + 4);
            *(uint4*)&sKl[d0] = a; *(uint4*)&sKl[d0 + 4] = c;
            a = *(const uint4*)(Vh + s0); c = *(const uint4*)(Vh + s0 + 4);
            *(uint4*)&sVh[d0] = a; *(uint4*)&sVh[d0 + 4] = c;
            a = *(const uint4*)(Vl + s0); c = *(const uint4*)(Vl + s0 + 4);
            *(uint4*)&sVl[d0] = a; *(uint4*)&sVl[d0 + 4] = c;
        }
        __syncthreads();

        float sacc[8][4];
        #pragma unroll
        for (int i = 0; i < 8; i++)
            #pragma unroll
            for (int j = 0; j < 4; j++) sacc[i][j] = 0.f;

        #pragma unroll
        for (int ks = 0; ks < 4; ks++) {
            #pragma unroll
            for (int ntp = 0; ntp < 4; ntp++) {
                int row = (ntp << 4) + ((g8 & 2) ? 8 : 0) + l8;
                int col = (ks << 3) + ((g8 & 1) ? 4 : 0);
                uint32_t ah = (uint32_t)__cvta_generic_to_shared(&sKh[row * VLDU + col]);
                uint32_t al = (uint32_t)__cvta_generic_to_shared(&sKl[row * VLDU + col]);
                uint32_t h0, h1, h2, h3, l0, l1, l2, l3;
                ldm4(h0, h1, h2, h3, ah);
                ldm4(l0, l1, l2, l3, al);
                mma_bf16(sacc[2*ntp],   qal[ks], h0, h1);
                mma_bf16(sacc[2*ntp],   qah[ks], l0, l1);
                mma_bf16(sacc[2*ntp],   qah[ks], h0, h1);
                mma_bf16(sacc[2*ntp+1], qal[ks], h2, h3);
                mma_bf16(sacc[2*ntp+1], qah[ks], l2, l3);
                mma_bf16(sacc[2*ntp+1], qah[ks], h2, h3);
            }
        }

        {
            const uint32_t* mb = mbase + (kv0 >> 5);
            uint32_t w0a = mb[(size_t)r * WPR];
            uint32_t w0b = mb[(size_t)r * WPR + 1];
            uint32_t w1a = mb[(size_t)(r + 8) * WPR];
            uint32_t w1b = mb[(size_t)(r + 8) * WPR + 1];
            #pragma unroll
            for (int nt = 0; nt < 8; nt++) {
                uint32_t wlo = (nt < 4) ? w0a : w0b;
                uint32_t whi = (nt < 4) ? w1a : w1b;
                int base = ((nt & 3) << 3) + (qt << 1);
                sacc[nt][0] = ((wlo >> base)       & 1) ? sacc[nt][0] * 0.125f : -1e-9f;
                sacc[nt][1] = ((wlo >> (base + 1)) & 1) ? sacc[nt][1] * 0.125f : -1e-9f;
                sacc[nt][2] = ((whi >> base)       & 1) ? sacc[nt][2] * 0.125f : -1e-9f;
                sacc[nt][3] = ((whi >> (base + 1)) & 1) ? sacc[nt][3] * 0.125f : -1e-9f;
            }
        }

        float mx0 = -INFINITY, mx1 = -INFINITY;
        #pragma unroll
        for (int nt = 0; nt < 8; nt++) {
            mx0 = fmaxf(mx0, fmaxf(sacc[nt][0], sacc[nt][1]));
            mx1 = fmaxf(mx1, fmaxf(sacc[nt][2], sacc[nt][3]));
        }
        mx0 = fmaxf(mx0, __shfl_xor_sync(0xffffffffu, mx0, 1));
        mx0 = fmaxf(mx0, __shfl_xor_sync(0xffffffffu, mx0, 2));
        mx1 = fmaxf(mx1, __shfl_xor_sync(0xffffffffu, mx1, 1));
        mx1 = fmaxf(mx1, __shfl_xor_sync(0xffffffffu, mx1, 2));

        float mn0 = fmaxf(mi0, mx0), mn1 = fmaxf(mi1, mx1);
        float al0 = __expf(mi0 - mn0), al1 = __expf(mi1 - mn1);
        mi0 = mn0; mi1 = mn1;

        float rs0 = 0.f, rs1 = 0.f;
        #pragma unroll
        for (int nt = 0; nt < 8; nt++) {
            sacc[nt][0] = __expf(sacc[nt][0] - mn0);
            sacc[nt][1] = __expf(sacc[nt][1] - mn0);
            sacc[nt][2] = __expf(sacc[nt][2] - mn1);
            sacc[nt][3] = __expf(sacc[nt][3] - mn1);
            rs0 += sacc[nt][0] + sacc[nt][1];
            rs1 += sacc[nt][2] + sacc[nt][3];
        }
        rs0 += __shfl_xor_sync(0xffffffffu, rs0, 1);
        rs0 += __shfl_xor_sync(0xffffffffu, rs0, 2);
        rs1 += __shfl_xor_sync(0xffffffffu, rs1, 1);
        rs1 += __shfl_xor_sync(0xffffffffu, rs1, 2);

        li0 = li0 * al0 + rs0;
        li1 = li1 * al1 + rs1;
        #pragma unroll
        for (int nt = 0; nt < 8; nt++) {
            oacc[nt][0] *= al0; oacc[nt][1] *= al0;
            oacc[nt][2] *= al1; oacc[nt][3] *= al1;
        }

        uint32_t pah[4][4], pal[4][4];
        #pragma unroll
        for (int ks = 0; ks < 4; ks++) {
            pack_hl(sacc[2*ks][0],   sacc[2*ks][1],   pah[ks][0], pal[ks][0]);
            pack_hl(sacc[2*ks][2],   sacc[2*ks][3],   pah[ks][1], pal[ks][1]);
            pack_hl(sacc[2*ks+1][0], sacc[2*ks+1][1], pah[ks][2], pal[ks][2]);
            pack_hl(sacc[2*ks+1][2], sacc[2*ks+1][3], pah[ks][3], pal[ks][3]);
        }

        #pragma unroll
        for (int ks = 0; ks < 4; ks++) {
            #pragma unroll
            for (int ntp = 0; ntp < 4; ntp++) {
                int row = (ks << 4) + ((g8 & 1) ? 8 : 0) + l8;
                int col = (ntp << 3) + ((g8 & 2) ? 4 : 0);
                uint32_t ah = (uint32_t)__cvta_generic_to_shared(&sVh[row * VLDU + col]);
                uint32_t al = (uint32_t)__cvta_generic_to_shared(&sVl[row * VLDU + col]);
                uint32_t h0, h1, h2, h3, l0, l1, l2, l3;
                ldm4t(h0, h1, h2, h3, ah);
                ldm4t(l0, l1, l2, l3, al);
                mma_bf16(oacc[2*ntp],   pal[ks], h0, h1);
                mma_bf16(oacc[2*ntp],   pah[ks], l0, l1);
                mma_bf16(oacc[2*ntp],   pah[ks], h0, h1);
                mma_bf16(oacc[2*ntp+1], pal[ks], h2, h3);
                mma_bf16(oacc[2*ntp+1], pah[ks], l2, l3);
                mma_bf16(oacc[2*ntp+1], pah[ks], h2, h3);
            }
        }
        __syncthreads();
    }

    // epilogue: normalize, pack to bf16 hi/lo O [m][d/2]
    float inv0 = 1.0f / li0, inv1 = 1.0f / li1;
    size_t rowbase = (size_t)b * S_ + qw;
    uint32_t* Oh = g_Oh + rowbase * KU_ + (h << 5);
    uint32_t* Ol = g_Ol + rowbase * KU_ + (h << 5);
    #pragma unroll
    for (int nt = 0; nt < 8; nt++) {
        int cu = (nt << 2) + qt;     // uint col within head (0..31)
        uint32_t hi, lo;
        pack_hl(oacc[nt][0] * inv0, oacc[nt][1] * inv0, hi, lo);
        Oh[(size_t)r * KU_ + cu] = hi;
        Ol[(size_t)r * KU_ + cu] = lo;
        pack_hl(oacc[nt][2] * inv1, oacc[nt][3] * inv1, hi, lo);
        Oh[(size_t)(r + 8) * KU_ + cu] = hi;
        Ol[(size_t)(r + 8) * KU_ + cu] = lo;
    }
}

// ---------------------------------------------------------------------------
extern "C" void kernel_launch(void* const* d_in, const int* in_sizes, int n_in,
                              void* d_out, int out_size)
{
    const float* X    = (const float*)d_in[0];
    const int*   mask = (const int*)d_in[1];
    const float* Wq   = (const float*)d_in[2];
    const float* Wk   = (const float*)d_in[3];
    const float* Wv   = (const float*)d_in[4];
    const float* Wo   = (const float*)d_in[5];
    float* out = (float*)d_out;

    pack_mask<<<2048, 256>>>(mask);
    prep_split<<<1184, 256>>>(X,  0, M_ * KU_);
    prep_split<<<1184, 256>>>(Wq, 1, WSZ);
    prep_split<<<1184, 256>>>(Wk, 2, WSZ);
    prep_split<<<1184, 256>>>(Wv, 3, WSZ);
    prep_split<<<1184, 256>>>(Wo, 4, WSZ);

    gemm_bf16<<<dim3(D_/128, M_/128, 3), 256>>>(nullptr, 0);
    attn_tc<<<dim3(S_ / 128, B_ * H_), 256>>>();
    gemm_bf16<<<dim3(D_/128, M_/128, 1), 256>>>(out, 3);
}